// round 17
// baseline (speedup 1.0000x reference)
#include <cuda_runtime.h>
#include <cuda_bf16.h>

// Shapes (fixed): B=2, N=2048, K=48, A=4
// X: (B,N,4,3) f32; edge_idx: (B,N,48) i32; C: (B,N) i32
// out: (B,N,48,192) f32
//
// R = Q*diag(s): Q orthonormal, s_y=||n_y||. Atoms rotated once by Q^T and
// PRE-MASKED (coords *= mk in {0,1} -> masked diff gives exactly 0 output).
// Per pair: diff + rsqrt + per-axis s_y.
//
// Phase 3: lane owns 4 consecutive pairs = 12 contiguous output floats
// = 3 contiguous 16B-aligned float4s -> stored DIRECTLY with 3 STG.128
// (48B lane chunks). No scratch, no syncwarp, minimal smem.
// Warp covers 2 k-rows per pass, 2 passes.

#define BB 2
#define NN 2048
#define KK 48
#define EPS 0.1f
#define THREADS 384
#define ROWF 24

__global__ __launch_bounds__(THREADS) void edge_orient_v17_kernel(
    const float* __restrict__ X,
    const int*   __restrict__ E,
    const int*   __restrict__ C,
    float*       __restrict__ out)
{
    const int bn   = blockIdx.x;
    const int b    = bn >> 11;        // / NN
    const int t    = threadIdx.x;
    const int w    = t >> 5;
    const int lane = t & 31;

    __shared__ __align__(16) float sA[KK * ROWF];   // rotated+masked coords
    __shared__ int   sJ[KK];
    __shared__ float sR[9];
    __shared__ float sS[3];

    const int* e_row = E + (size_t)bn * KK;

    // ---- phase 1: raw coords + neighbor idx + frame ----
    if (t < KK) sJ[t] = e_row[t];
    if (t < KK * 6) {
        const int k  = t / 6;
        const int qq = t - k * 6;
        if (qq < 3) {
            ((float4*)&sA[k * ROWF])[qq] = ((const float4*)(X + (size_t)bn * 12))[qq];
        } else {
            const int j = e_row[k];
            ((float4*)&sA[k * ROWF])[qq] =
                ((const float4*)(X + ((size_t)(b * NN + j)) * 12))[qq - 3];
        }
    }
    if (t == 336) {
        const float* xr = X + (size_t)bn * 12;
        float Nx = xr[0], Ny = xr[1], Nz = xr[2];
        float Ax = xr[3], Ay = xr[4], Az = xr[5];
        float Cx = xr[6], Cy = xr[7], Cz = xr[8];

        float ux = Nx - Ax, uy = Ny - Ay, uz = Nz - Az;
        float invE = rsqrtf(ux*ux + uy*uy + uz*uz + EPS);
        float n1x = ux*invE, n1y = uy*invE, n1z = uz*invE;
        float n1n2 = n1x*n1x + n1y*n1y + n1z*n1z;
        float inv0 = rsqrtf(n1n2);
        float q1x = n1x*inv0, q1y = n1y*inv0, q1z = n1z*inv0;
        float s1  = n1n2 * inv0;

        float vx = Cx - Ax, vy = Cy - Ay, vz = Cz - Az;
        float invV = rsqrtf(vx*vx + vy*vy + vz*vz + EPS);
        vx *= invV; vy *= invV; vz *= invV;

        float c2x = n1y*vz - n1z*vy;
        float c2y = n1z*vx - n1x*vz;
        float c2z = n1x*vy - n1y*vx;
        invE = rsqrtf(c2x*c2x + c2y*c2y + c2z*c2z + EPS);
        float n2x = c2x*invE, n2y = c2y*invE, n2z = c2z*invE;
        float n2n2 = n2x*n2x + n2y*n2y + n2z*n2z;
        inv0 = rsqrtf(n2n2);
        float q2x = n2x*inv0, q2y = n2y*inv0, q2z = n2z*inv0;
        float s2  = n2n2 * inv0;

        float c3x = n1y*n2z - n1z*n2y;
        float c3y = n1z*n2x - n1x*n2z;
        float c3z = n1x*n2y - n1y*n2x;
        invE = rsqrtf(c3x*c3x + c3y*c3y + c3z*c3z + EPS);
        float n3x = c3x*invE, n3y = c3y*invE, n3z = c3z*invE;
        float n3n2 = n3x*n3x + n3y*n3y + n3z*n3z;
        inv0 = rsqrtf(n3n2);

        sR[0] = q1x;      sR[1] = q1y;      sR[2] = q1z;
        sR[3] = q2x;      sR[4] = q2y;      sR[5] = q2z;
        sR[6] = n3x*inv0; sR[7] = n3y*inv0; sR[8] = n3z*inv0;
        sS[0] = s1; sS[1] = s2; sS[2] = n3n2 * inv0;
    }
    __syncthreads();

    // ---- phase 2: rotate + mask all atoms in place ----
    {
        const int k = t >> 3;
        const int a = (t & 7) * 3;
        const int j = sJ[k];
        const float mk = ((C[bn] > 0) && (C[b * NN + j] > 0)) ? 1.0f : 0.0f;
        float* p = &sA[k * ROWF + a];
        const float x = p[0], y = p[1], z = p[2];
        const float rx = (x*sR[0] + y*sR[1] + z*sR[2]) * mk;
        const float ry = (x*sR[3] + y*sR[4] + z*sR[5]) * mk;
        const float rz = (x*sR[6] + y*sR[7] + z*sR[8]) * mk;
        __syncthreads();
        p[0] = rx; p[1] = ry; p[2] = rz;
    }
    __syncthreads();

    const float s1 = sS[0], s2 = sS[1], s3 = sS[2];

    // ---- phase 3: lane = 4 pairs = 3 contiguous output float4s ----
    const int rowsel = lane >> 4;            // which of the warp's 2 rows
    const int aIdx   = (lane & 15) >> 1;     // a atom 0..7
    const int bBase  = (lane & 1) * 4;       // b in {0..3} or {4..7}

    // output float4 offset of this lane's chunk within its row:
    // pair s = 8*aIdx + bBase -> float 3*s = 24*aIdx + 12*(lane&1)
    const int chunk4 = 6 * aIdx + 3 * (lane & 1);   // float4 index in row

    float4* obase = (float4*)(out + (size_t)bn * (KK * 192));

#pragma unroll
    for (int pass = 0; pass < 2; pass++) {
        const int rp  = w + 12 * pass;        // row-pair 0..23
        const int row = 2 * rp + rowsel;      // this lane's k row

        const float* rbase = &sA[row * ROWF];
        const float ax = rbase[3 * aIdx + 0];
        const float ay = rbase[3 * aIdx + 1];
        const float az = rbase[3 * aIdx + 2];

        float v[12];
#pragma unroll
        for (int i = 0; i < 4; i++) {
            const float* pb = rbase + 3 * (bBase + i);
            const float dx = pb[0] - ax;
            const float dy = pb[1] - ay;
            const float dz = pb[2] - az;
            float nn = fmaf(dx, dx, EPS);
            nn = fmaf(dy, dy, nn);
            nn = fmaf(dz, dz, nn);
            const float inv = rsqrtf(nn);
            v[3*i + 0] = dx * inv * s1;
            v[3*i + 1] = dy * inv * s2;
            v[3*i + 2] = dz * inv * s3;
        }

        // direct 48B chunk store: 3 contiguous STG.128
        float4* od = obase + row * 48 + chunk4;
        od[0] = make_float4(v[0], v[1], v[2],  v[3]);
        od[1] = make_float4(v[4], v[5], v[6],  v[7]);
        od[2] = make_float4(v[8], v[9], v[10], v[11]);
    }
}

extern "C" void kernel_launch(void* const* d_in, const int* in_sizes, int n_in,
                              void* d_out, int out_size) {
    const float* X = (const float*)d_in[0];
    const int*   E = (const int*)d_in[1];
    const int*   C = (const int*)d_in[2];
    float* out = (float*)d_out;

    edge_orient_v17_kernel<<<BB * NN, THREADS>>>(X, E, C, out);
}